// round 7
// baseline (speedup 1.0000x reference)
#include <cuda_runtime.h>

#define N_NODES 100000
#define N_EDGES 1600000
#define IN_DIM 128
#define HID 32
#define BN_EPS 1e-5f
#define CAP 96   // max in-degree capacity (Poisson(16)); %16==0 for padded chunks

// packed fp32x2 FMA (sm_103a FFMA2) — only reachable via PTX
#define FMA2(d, a, b) asm("fma.rn.f32x2 %0, %1, %2, %0;" : "+l"(d) : "l"(a), "l"(b))

// ---- scratch (static device globals; no allocation allowed) ----
// hs arrays have one extra row (index N_NODES) that is NEVER written:
// __device__ globals are zero-initialized, so it is a permanent zero row
// used as the padding target for branch-free gathers.
__device__ __align__(128) int   g_cnt[N_NODES];              // in-degree (excl. self loop)
__device__ __align__(128) int   g_slots[N_NODES * CAP];      // buckets: src ids per dst
__device__ __align__(128) float g_hs1[(N_NODES + 1) * HID];  // (x@W1)*dinv[row] + zero row
__device__ __align__(128) float g_z1[N_NODES * HID];         // conv1 result pre-bias
__device__ __align__(128) float g_hs2[(N_NODES + 1) * HID];  // (z@W2)*dinv[row] + zero row
__device__ float g_sums[64];                                 // [0:32) sum, [32:64) sumsq
__device__ float g_bn[64];                                   // [0:32) scale, [32:64) shift

// ---------------------------------------------------------------
// 1) init
__global__ void k_init() {
    int i = blockIdx.x * blockDim.x + threadIdx.x;
    if (i < N_NODES) g_cnt[i] = 0;
    if (i < 64) g_sums[i] = 0.0f;
}

// 2) fill: bucket src ids by dst (4 edges per thread, vector index loads)
__global__ void k_fill(const int* __restrict__ src, const int* __restrict__ dst) {
    int t = blockIdx.x * blockDim.x + threadIdx.x;
    int e0 = t * 4;
    if (e0 >= N_EDGES) return;
    int4 d4 = *(const int4*)&dst[e0];
    int4 s4 = *(const int4*)&src[e0];
    int pos;
    pos = atomicAdd(&g_cnt[d4.x], 1); if (pos < CAP) g_slots[d4.x * CAP + pos] = s4.x;
    pos = atomicAdd(&g_cnt[d4.y], 1); if (pos < CAP) g_slots[d4.y * CAP + pos] = s4.y;
    pos = atomicAdd(&g_cnt[d4.z], 1); if (pos < CAP) g_slots[d4.z * CAP + pos] = s4.z;
    pos = atomicAdd(&g_cnt[d4.w], 1); if (pos < CAP) g_slots[d4.w * CAP + pos] = s4.w;
}

// 2b) pad: fill slots[rem .. round16(rem)) with the zero-row index.
__global__ void k_pad() {
    int t = blockIdx.x * blockDim.x + threadIdx.x;
    int n = t >> 4;
    int l = t & 15;
    if (n >= N_NODES) return;
    int rem = min(g_cnt[n], CAP);
    int padded = (rem + 15) & ~15;
    int j = rem + l;
    if (j < padded) g_slots[n * CAP + j] = N_NODES;   // zero row
}

// ---------------------------------------------------------------
// 3) GEMM1 (FFMA2): hs1[r] = (x[r] @ W1) * dinv[r]
//    128 rows x 32 cols per block; thread computes 4 rows x 4 cols as
//    f32x2 row-pairs. Xs stored k-major (row pairs contiguous), W duplicated
//    per-channel so both FFMA2 operands load pre-packed from smem.
__global__ void __launch_bounds__(256) k_gemm1(const float* __restrict__ x,
                                               const float* __restrict__ W1) {
    __shared__ __align__(16) float  Xs_t[32 * 136];   // [k][r], 17.4KB
    __shared__ __align__(16) float2 Wd[32 * 34];      // [k][c] dup pairs, 8.7KB
    int tid = threadIdx.x;
    int rowbase = blockIdx.x * 128;
    int cg = tid & 7;    // cols cg*4..cg*4+3
    int rg = tid >> 3;   // rows rg*4..rg*4+3

    unsigned long long acc01[4] = {0ull, 0ull, 0ull, 0ull};  // rows (+0,+1) x 4 cols
    unsigned long long acc23[4] = {0ull, 0ull, 0ull, 0ull};  // rows (+2,+3) x 4 cols

    for (int kb = 0; kb < IN_DIM; kb += 32) {
        __syncthreads();
        // stage W chunk duplicated: Wd[k][c] = (w, w)
        #pragma unroll
        for (int t = 0; t < 4; t++) {
            int e = tid + t * 256;
            int k = e >> 5, c = e & 31;
            float w = W1[(kb + k) * HID + c];
            Wd[k * 34 + c] = make_float2(w, w);
        }
        // stage X chunk transposed: Xs_t[k][r]  (lane = row -> conflict-free STS)
        #pragma unroll
        for (int t = 0; t < 4; t++) {
            int e = tid + t * 256;
            int q = e >> 7, r = e & 127;
            int gr = rowbase + r;
            float4 v = make_float4(0.f, 0.f, 0.f, 0.f);
            if (gr < N_NODES) v = *(const float4*)&x[(size_t)gr * IN_DIM + kb + q * 4];
            Xs_t[(q * 4 + 0) * 136 + r] = v.x;
            Xs_t[(q * 4 + 1) * 136 + r] = v.y;
            Xs_t[(q * 4 + 2) * 136 + r] = v.z;
            Xs_t[(q * 4 + 3) * 136 + r] = v.w;
        }
        __syncthreads();
        #pragma unroll
        for (int k = 0; k < 32; k++) {
            ulonglong2 xq = *(const ulonglong2*)&Xs_t[k * 136 + rg * 4];  // rows (0,1),(2,3)
            ulonglong2 w0 = *(const ulonglong2*)&Wd[k * 34 + cg * 4];      // cols 0,1 dup
            ulonglong2 w1 = *(const ulonglong2*)&Wd[k * 34 + cg * 4 + 2];  // cols 2,3 dup
            FMA2(acc01[0], xq.x, w0.x);
            FMA2(acc01[1], xq.x, w0.y);
            FMA2(acc01[2], xq.x, w1.x);
            FMA2(acc01[3], xq.x, w1.y);
            FMA2(acc23[0], xq.y, w0.x);
            FMA2(acc23[1], xq.y, w0.y);
            FMA2(acc23[2], xq.y, w1.x);
            FMA2(acc23[3], xq.y, w1.y);
        }
    }

    // unpack: acc01[c] = (row+0, row+1), acc23[c] = (row+2, row+3)
    float o[4][4];
    #pragma unroll
    for (int c = 0; c < 4; c++) {
        o[0][c] = __uint_as_float((unsigned)(acc01[c] & 0xffffffffull));
        o[1][c] = __uint_as_float((unsigned)(acc01[c] >> 32));
        o[2][c] = __uint_as_float((unsigned)(acc23[c] & 0xffffffffull));
        o[3][c] = __uint_as_float((unsigned)(acc23[c] >> 32));
    }
    #pragma unroll
    for (int ri = 0; ri < 4; ri++) {
        int r = rowbase + rg * 4 + ri;
        if (r < N_NODES) {
            float dinv = rsqrtf(1.0f + (float)g_cnt[r]);
            float4 v = make_float4(o[ri][0] * dinv, o[ri][1] * dinv,
                                   o[ri][2] * dinv, o[ri][3] * dinv);
            *(float4*)&g_hs1[(size_t)r * HID + cg * 4] = v;
        }
    }
}

// ---------------------------------------------------------------
// pull body: one warp per node, 4 subwarps x 8 lanes; slot list padded to
// multiple of 16 with zero-row index -> branch-free 16-edge chunks.
__device__ __forceinline__ float4 pull_node(const float* __restrict__ hs, int n, int lane) {
    int cnt = g_cnt[n];
    int rem = min(cnt, CAP);
    int padded = (rem + 15) & ~15;
    int sw = lane >> 3;          // subwarp 0..3
    int q  = lane & 7;           // float4 slot within row
    const int* base = &g_slots[(size_t)n * CAP];

    float4 acc;
    if (sw == 0) {               // self loop handled by subwarp 0
        acc = *(const float4*)&hs[(size_t)n * HID + q * 4];
    } else {
        acc = make_float4(0.f, 0.f, 0.f, 0.f);
    }

    for (int j0 = 0; j0 < padded; j0 += 16) {
        int s0 = base[j0 +  0 + sw];
        int s1 = base[j0 +  4 + sw];
        int s2 = base[j0 +  8 + sw];
        int s3 = base[j0 + 12 + sw];
        float4 v0 = *(const float4*)&hs[(size_t)s0 * HID + q * 4];
        float4 v1 = *(const float4*)&hs[(size_t)s1 * HID + q * 4];
        float4 v2 = *(const float4*)&hs[(size_t)s2 * HID + q * 4];
        float4 v3 = *(const float4*)&hs[(size_t)s3 * HID + q * 4];
        acc.x += v0.x; acc.y += v0.y; acc.z += v0.z; acc.w += v0.w;
        acc.x += v1.x; acc.y += v1.y; acc.z += v1.z; acc.w += v1.w;
        acc.x += v2.x; acc.y += v2.y; acc.z += v2.z; acc.w += v2.w;
        acc.x += v3.x; acc.y += v3.y; acc.z += v3.z; acc.w += v3.w;
    }

    #pragma unroll
    for (int off = 8; off <= 16; off <<= 1) {
        acc.x += __shfl_xor_sync(0xffffffffu, acc.x, off);
        acc.y += __shfl_xor_sync(0xffffffffu, acc.y, off);
        acc.z += __shfl_xor_sync(0xffffffffu, acc.z, off);
        acc.w += __shfl_xor_sync(0xffffffffu, acc.w, off);
    }
    float dinv = rsqrtf(1.0f + (float)cnt);
    acc.x *= dinv; acc.y *= dinv; acc.z *= dinv; acc.w *= dinv;
    return acc;
}

// 4) pull1
__global__ void k_pull1() {
    int w = (blockIdx.x * blockDim.x + threadIdx.x) >> 5;
    int lane = threadIdx.x & 31;
    if (w >= N_NODES) return;
    float4 r = pull_node(g_hs1, w, lane);
    if (lane < 8)
        *(float4*)&g_z1[(size_t)w * HID + lane * 4] = r;
}

// 8) pull2
__global__ void k_pull2(const float* __restrict__ b2, float* __restrict__ out) {
    int w = (blockIdx.x * blockDim.x + threadIdx.x) >> 5;
    int lane = threadIdx.x & 31;
    if (w >= N_NODES) return;
    float4 r = pull_node(g_hs2, w, lane);
    if (lane < 8) {
        float4 bb = *(const float4*)&b2[lane * 4];
        r.x += bb.x; r.y += bb.y; r.z += bb.z; r.w += bb.w;
        *(float4*)&out[(size_t)w * HID + lane * 4] = r;
    }
}

// ---------------------------------------------------------------
// 5) BN stats over v = z1 + b1
__global__ void k_bnstats(const float* __restrict__ b1) {
    __shared__ float ss[256], sq[256];
    int tid = threadIdx.x;
    int c = tid & 31, rs = tid >> 5;
    int chunk = (N_NODES + gridDim.x - 1) / gridDim.x;
    int r0 = blockIdx.x * chunk;
    int r1 = min(r0 + chunk, N_NODES);
    float bc = b1[c];
    float s = 0.f, s2 = 0.f;
    for (int r = r0 + rs; r < r1; r += 8) {
        float v = g_z1[(size_t)r * HID + c] + bc;
        s += v; s2 += v * v;
    }
    ss[tid] = s; sq[tid] = s2;
    __syncthreads();
    if (tid < 128) { ss[tid] += ss[tid + 128]; sq[tid] += sq[tid + 128]; }
    __syncthreads();
    if (tid < 64) { ss[tid] += ss[tid + 64]; sq[tid] += sq[tid + 64]; }
    __syncthreads();
    if (tid < 32) {
        atomicAdd(&g_sums[c], ss[tid] + ss[tid + 32]);
        atomicAdd(&g_sums[32 + c], sq[tid] + sq[tid + 32]);
    }
}

// 6) BN finalize
__global__ void k_bnfin(const float* __restrict__ gamma, const float* __restrict__ beta) {
    int c = threadIdx.x;
    if (c < 32) {
        float mean = g_sums[c] * (1.0f / N_NODES);
        float var = g_sums[32 + c] * (1.0f / N_NODES) - mean * mean;
        var = fmaxf(var, 0.f);
        float sc = gamma[c] * rsqrtf(var + BN_EPS);
        g_bn[c] = sc;
        g_bn[32 + c] = beta[c] - mean * sc;
    }
}

// ---------------------------------------------------------------
// 7) GEMM2: z = relu(BN(z1 + b1)); hs2 = (z@W2)*dinv
__global__ void k_gemm2(const float* __restrict__ b1, const float* __restrict__ W2) {
    __shared__ float Ws[HID * HID];   // 4KB
    __shared__ float Zs[128 * 36];    // 18KB
    __shared__ float sc_s[32], sh_s[32], bb_s[32];
    int tid = threadIdx.x;
    int rowbase = blockIdx.x * 128;

    if (tid < 32) { sc_s[tid] = g_bn[tid]; sh_s[tid] = g_bn[32 + tid]; bb_s[tid] = b1[tid]; }
    for (int i = tid; i < HID * HID / 4; i += 256)
        ((float4*)Ws)[i] = ((const float4*)W2)[i];
    __syncthreads();

    #pragma unroll
    for (int j = 0; j < 4; j++) {
        int idx = tid + j * 256;
        int r = idx >> 3, q = idx & 7;
        int gr = rowbase + r;
        float4 v = make_float4(0.f, 0.f, 0.f, 0.f);
        if (gr < N_NODES) {
            float4 a = *(const float4*)&g_z1[(size_t)gr * HID + q * 4];
            int c = q * 4;
            v.x = fmaxf(fmaf(a.x + bb_s[c + 0], sc_s[c + 0], sh_s[c + 0]), 0.f);
            v.y = fmaxf(fmaf(a.y + bb_s[c + 1], sc_s[c + 1], sh_s[c + 1]), 0.f);
            v.z = fmaxf(fmaf(a.z + bb_s[c + 2], sc_s[c + 2], sh_s[c + 2]), 0.f);
            v.w = fmaxf(fmaf(a.w + bb_s[c + 3], sc_s[c + 3], sh_s[c + 3]), 0.f);
        }
        *(float4*)&Zs[r * 36 + q * 4] = v;
    }
    __syncthreads();

    int cg = tid & 7, rg = tid >> 3;
    float acc[4][4] = {};
    #pragma unroll
    for (int k = 0; k < 32; k++) {
        float4 b4 = *(const float4*)&Ws[k * HID + cg * 4];
        #pragma unroll
        for (int ri = 0; ri < 4; ri++) {
            float a = Zs[(rg * 4 + ri) * 36 + k];
            acc[ri][0] += a * b4.x; acc[ri][1] += a * b4.y;
            acc[ri][2] += a * b4.z; acc[ri][3] += a * b4.w;
        }
    }
    #pragma unroll
    for (int ri = 0; ri < 4; ri++) {
        int r = rowbase + rg * 4 + ri;
        if (r < N_NODES) {
            float dinv = rsqrtf(1.0f + (float)g_cnt[r]);
            float4 v = make_float4(acc[ri][0] * dinv, acc[ri][1] * dinv,
                                   acc[ri][2] * dinv, acc[ri][3] * dinv);
            *(float4*)&g_hs2[r * HID + cg * 4] = v;
        }
    }
}

// ---------------------------------------------------------------
extern "C" void kernel_launch(void* const* d_in, const int* in_sizes, int n_in,
                              void* d_out, int out_size) {
    const float* x     = (const float*)d_in[0];
    const int*   ei    = (const int*)d_in[1];   // int32
    const float* W1    = (const float*)d_in[2];
    const float* b1    = (const float*)d_in[3];
    const float* gamma = (const float*)d_in[4];
    const float* beta  = (const float*)d_in[5];
    const float* W2    = (const float*)d_in[6];
    const float* b2    = (const float*)d_in[7];
    float* out = (float*)d_out;

    const int* esrc = ei;
    const int* edst = ei + N_EDGES;

    k_init   <<<(N_NODES + 255) / 256, 256>>>();
    k_fill   <<<(N_EDGES / 4 + 255) / 256, 256>>>(esrc, edst);
    k_pad    <<<(N_NODES * 16 + 255) / 256, 256>>>();
    k_gemm1  <<<(N_NODES + 127) / 128, 256>>>(x, W1);
    k_pull1  <<<(N_NODES * 32) / 256, 256>>>();
    k_bnstats<<<592, 256>>>(b1);
    k_bnfin  <<<1, 32>>>(gamma, beta);
    k_gemm2  <<<(N_NODES + 127) / 128, 256>>>(b1, W2);
    k_pull2  <<<(N_NODES * 32) / 256, 256>>>(b2, out);
}

// round 8
// speedup vs baseline: 1.2100x; 1.2100x over previous
#include <cuda_runtime.h>

#define N_NODES 100000
#define N_EDGES 1600000
#define IN_DIM 128
#define HID 32
#define BN_EPS 1e-5f
#define CAP 96      // max in-degree capacity; %32==0 for padded chunks
#define PCHUNK 32   // pull chunk: pad slot lists to multiple of 32 -> MLP 8

// ---- scratch (static device globals; no allocation allowed) ----
// hs arrays have one extra row (index N_NODES) that is NEVER written:
// zero-initialized -> permanent zero row used as padding target.
__device__ __align__(128) int   g_cnt[N_NODES];
__device__ __align__(128) int   g_slots[N_NODES * CAP];
__device__ __align__(128) float g_hs1[(N_NODES + 1) * HID];
__device__ __align__(128) float g_z1[N_NODES * HID];
__device__ __align__(128) float g_hs2[(N_NODES + 1) * HID];
__device__ float g_sums[64];
__device__ float g_bn[64];

// ---------------------------------------------------------------
__global__ void k_init() {
    int i = blockIdx.x * blockDim.x + threadIdx.x;
    if (i < N_NODES) g_cnt[i] = 0;
    if (i < 64) g_sums[i] = 0.0f;
}

__global__ void k_fill(const int* __restrict__ src, const int* __restrict__ dst) {
    int t = blockIdx.x * blockDim.x + threadIdx.x;
    int e0 = t * 4;
    if (e0 >= N_EDGES) return;
    int4 d4 = *(const int4*)&dst[e0];
    int4 s4 = *(const int4*)&src[e0];
    int pos;
    pos = atomicAdd(&g_cnt[d4.x], 1); if (pos < CAP) g_slots[d4.x * CAP + pos] = s4.x;
    pos = atomicAdd(&g_cnt[d4.y], 1); if (pos < CAP) g_slots[d4.y * CAP + pos] = s4.y;
    pos = atomicAdd(&g_cnt[d4.z], 1); if (pos < CAP) g_slots[d4.z * CAP + pos] = s4.z;
    pos = atomicAdd(&g_cnt[d4.w], 1); if (pos < CAP) g_slots[d4.w * CAP + pos] = s4.w;
}

// pad slots[rem .. round32(rem)) with zero-row index; 32 lanes per node
__global__ void k_pad() {
    int t = blockIdx.x * blockDim.x + threadIdx.x;
    int n = t >> 5;
    int l = t & 31;
    if (n >= N_NODES) return;
    int rem = min(g_cnt[n], CAP);
    int padded = (rem + PCHUNK - 1) & ~(PCHUNK - 1);
    int j = rem + l;
    if (j < padded) g_slots[n * CAP + j] = N_NODES;   // zero row
}

// ---------------------------------------------------------------
// 3) GEMM1: hs1[r] = (x[r] @ W1) * dinv[r]
//    128 rows x 32 cols per block; 4x4 thread tile; inner loop does 4 k per
//    step with float4 LDS for both X and W (72 instrs / 64 FMA per 4k).
__global__ void __launch_bounds__(256) k_gemm1(const float* __restrict__ x,
                                               const float* __restrict__ W1) {
    __shared__ float Ws[IN_DIM * HID];   // 16KB
    __shared__ float Xs[128 * 36];       // 18KB (144B rows: 16B-aligned, 2-way max)
    int tid = threadIdx.x;
    int rowbase = blockIdx.x * 128;

    for (int i = tid; i < IN_DIM * HID / 4; i += 256)
        ((float4*)Ws)[i] = ((const float4*)W1)[i];

    int cg = tid & 7;    // cols cg*4..cg*4+3
    int rg = tid >> 3;   // rows rg*4..rg*4+3
    float acc[4][4] = {};

    for (int kb = 0; kb < IN_DIM; kb += 32) {
        __syncthreads();
        #pragma unroll
        for (int j = 0; j < 4; j++) {
            int idx = tid + j * 256;
            int r = idx >> 3, q = idx & 7;
            int gr = rowbase + r;
            float4 v = make_float4(0.f, 0.f, 0.f, 0.f);
            if (gr < N_NODES) v = *(const float4*)&x[(size_t)gr * IN_DIM + kb + q * 4];
            *(float4*)&Xs[r * 36 + q * 4] = v;
        }
        __syncthreads();
        #pragma unroll
        for (int kq = 0; kq < 8; kq++) {
            float4 b0 = *(const float4*)&Ws[(kb + kq * 4 + 0) * HID + cg * 4];
            float4 b1 = *(const float4*)&Ws[(kb + kq * 4 + 1) * HID + cg * 4];
            float4 b2 = *(const float4*)&Ws[(kb + kq * 4 + 2) * HID + cg * 4];
            float4 b3 = *(const float4*)&Ws[(kb + kq * 4 + 3) * HID + cg * 4];
            #pragma unroll
            for (int ri = 0; ri < 4; ri++) {
                float4 a4 = *(const float4*)&Xs[(rg * 4 + ri) * 36 + kq * 4];
                acc[ri][0] += a4.x * b0.x; acc[ri][1] += a4.x * b0.y;
                acc[ri][2] += a4.x * b0.z; acc[ri][3] += a4.x * b0.w;
                acc[ri][0] += a4.y * b1.x; acc[ri][1] += a4.y * b1.y;
                acc[ri][2] += a4.y * b1.z; acc[ri][3] += a4.y * b1.w;
                acc[ri][0] += a4.z * b2.x; acc[ri][1] += a4.z * b2.y;
                acc[ri][2] += a4.z * b2.z; acc[ri][3] += a4.z * b2.w;
                acc[ri][0] += a4.w * b3.x; acc[ri][1] += a4.w * b3.y;
                acc[ri][2] += a4.w * b3.z; acc[ri][3] += a4.w * b3.w;
            }
        }
    }
    #pragma unroll
    for (int ri = 0; ri < 4; ri++) {
        int r = rowbase + rg * 4 + ri;
        if (r < N_NODES) {
            float dinv = rsqrtf(1.0f + (float)g_cnt[r]);
            float4 v = make_float4(acc[ri][0] * dinv, acc[ri][1] * dinv,
                                   acc[ri][2] * dinv, acc[ri][3] * dinv);
            *(float4*)&g_hs1[(size_t)r * HID + cg * 4] = v;
        }
    }
}

// ---------------------------------------------------------------
// pull body: one warp per node, 4 subwarps x 8 lanes; slot lists padded to a
// multiple of 32 with the zero-row index -> branch-free 32-edge chunks with
// 8 independent gathers in flight (MLP 8). Typical node = ONE iteration.
__device__ __forceinline__ float4 pull_node(const float* __restrict__ hs, int n, int lane) {
    int cnt = g_cnt[n];
    int rem = min(cnt, CAP);
    int padded = (rem + PCHUNK - 1) & ~(PCHUNK - 1);
    int sw = lane >> 3;          // subwarp 0..3
    int q  = lane & 7;           // float4 slot within row
    const int* base = &g_slots[(size_t)n * CAP];

    float4 acc;
    if (sw == 0) {               // self loop handled by subwarp 0
        acc = *(const float4*)&hs[(size_t)n * HID + q * 4];
    } else {
        acc = make_float4(0.f, 0.f, 0.f, 0.f);
    }

    for (int j0 = 0; j0 < padded; j0 += PCHUNK) {
        int s0 = base[j0 +  0 + sw];
        int s1 = base[j0 +  4 + sw];
        int s2 = base[j0 +  8 + sw];
        int s3 = base[j0 + 12 + sw];
        int s4 = base[j0 + 16 + sw];
        int s5 = base[j0 + 20 + sw];
        int s6 = base[j0 + 24 + sw];
        int s7 = base[j0 + 28 + sw];
        float4 v0 = *(const float4*)&hs[(size_t)s0 * HID + q * 4];
        float4 v1 = *(const float4*)&hs[(size_t)s1 * HID + q * 4];
        float4 v2 = *(const float4*)&hs[(size_t)s2 * HID + q * 4];
        float4 v3 = *(const float4*)&hs[(size_t)s3 * HID + q * 4];
        float4 v4 = *(const float4*)&hs[(size_t)s4 * HID + q * 4];
        float4 v5 = *(const float4*)&hs[(size_t)s5 * HID + q * 4];
        float4 v6 = *(const float4*)&hs[(size_t)s6 * HID + q * 4];
        float4 v7 = *(const float4*)&hs[(size_t)s7 * HID + q * 4];
        acc.x += v0.x; acc.y += v0.y; acc.z += v0.z; acc.w += v0.w;
        acc.x += v1.x; acc.y += v1.y; acc.z += v1.z; acc.w += v1.w;
        acc.x += v2.x; acc.y += v2.y; acc.z += v2.z; acc.w += v2.w;
        acc.x += v3.x; acc.y += v3.y; acc.z += v3.z; acc.w += v3.w;
        acc.x += v4.x; acc.y += v4.y; acc.z += v4.z; acc.w += v4.w;
        acc.x += v5.x; acc.y += v5.y; acc.z += v5.z; acc.w += v5.w;
        acc.x += v6.x; acc.y += v6.y; acc.z += v6.z; acc.w += v6.w;
        acc.x += v7.x; acc.y += v7.y; acc.z += v7.z; acc.w += v7.w;
    }

    #pragma unroll
    for (int off = 8; off <= 16; off <<= 1) {
        acc.x += __shfl_xor_sync(0xffffffffu, acc.x, off);
        acc.y += __shfl_xor_sync(0xffffffffu, acc.y, off);
        acc.z += __shfl_xor_sync(0xffffffffu, acc.z, off);
        acc.w += __shfl_xor_sync(0xffffffffu, acc.w, off);
    }
    float dinv = rsqrtf(1.0f + (float)cnt);
    acc.x *= dinv; acc.y *= dinv; acc.z *= dinv; acc.w *= dinv;
    return acc;
}

__global__ void k_pull1() {
    int w = (blockIdx.x * blockDim.x + threadIdx.x) >> 5;
    int lane = threadIdx.x & 31;
    if (w >= N_NODES) return;
    float4 r = pull_node(g_hs1, w, lane);
    if (lane < 8)
        *(float4*)&g_z1[(size_t)w * HID + lane * 4] = r;
}

__global__ void k_pull2(const float* __restrict__ b2, float* __restrict__ out) {
    int w = (blockIdx.x * blockDim.x + threadIdx.x) >> 5;
    int lane = threadIdx.x & 31;
    if (w >= N_NODES) return;
    float4 r = pull_node(g_hs2, w, lane);
    if (lane < 8) {
        float4 bb = *(const float4*)&b2[lane * 4];
        r.x += bb.x; r.y += bb.y; r.z += bb.z; r.w += bb.w;
        *(float4*)&out[(size_t)w * HID + lane * 4] = r;
    }
}

// ---------------------------------------------------------------
__global__ void k_bnstats(const float* __restrict__ b1) {
    __shared__ float ss[256], sq[256];
    int tid = threadIdx.x;
    int c = tid & 31, rs = tid >> 5;
    int chunk = (N_NODES + gridDim.x - 1) / gridDim.x;
    int r0 = blockIdx.x * chunk;
    int r1 = min(r0 + chunk, N_NODES);
    float bc = b1[c];
    float s = 0.f, s2 = 0.f;
    for (int r = r0 + rs; r < r1; r += 8) {
        float v = g_z1[(size_t)r * HID + c] + bc;
        s += v; s2 += v * v;
    }
    ss[tid] = s; sq[tid] = s2;
    __syncthreads();
    if (tid < 128) { ss[tid] += ss[tid + 128]; sq[tid] += sq[tid + 128]; }
    __syncthreads();
    if (tid < 64) { ss[tid] += ss[tid + 64]; sq[tid] += sq[tid + 64]; }
    __syncthreads();
    if (tid < 32) {
        atomicAdd(&g_sums[c], ss[tid] + ss[tid + 32]);
        atomicAdd(&g_sums[32 + c], sq[tid] + sq[tid + 32]);
    }
}

__global__ void k_bnfin(const float* __restrict__ gamma, const float* __restrict__ beta) {
    int c = threadIdx.x;
    if (c < 32) {
        float mean = g_sums[c] * (1.0f / N_NODES);
        float var = g_sums[32 + c] * (1.0f / N_NODES) - mean * mean;
        var = fmaxf(var, 0.f);
        float sc = gamma[c] * rsqrtf(var + BN_EPS);
        g_bn[c] = sc;
        g_bn[32 + c] = beta[c] - mean * sc;
    }
}

// ---------------------------------------------------------------
__global__ void k_gemm2(const float* __restrict__ b1, const float* __restrict__ W2) {
    __shared__ float Ws[HID * HID];
    __shared__ float Zs[128 * 36];
    __shared__ float sc_s[32], sh_s[32], bb_s[32];
    int tid = threadIdx.x;
    int rowbase = blockIdx.x * 128;

    if (tid < 32) { sc_s[tid] = g_bn[tid]; sh_s[tid] = g_bn[32 + tid]; bb_s[tid] = b1[tid]; }
    for (int i = tid; i < HID * HID / 4; i += 256)
        ((float4*)Ws)[i] = ((const float4*)W2)[i];
    __syncthreads();

    #pragma unroll
    for (int j = 0; j < 4; j++) {
        int idx = tid + j * 256;
        int r = idx >> 3, q = idx & 7;
        int gr = rowbase + r;
        float4 v = make_float4(0.f, 0.f, 0.f, 0.f);
        if (gr < N_NODES) {
            float4 a = *(const float4*)&g_z1[(size_t)gr * HID + q * 4];
            int c = q * 4;
            v.x = fmaxf(fmaf(a.x + bb_s[c + 0], sc_s[c + 0], sh_s[c + 0]), 0.f);
            v.y = fmaxf(fmaf(a.y + bb_s[c + 1], sc_s[c + 1], sh_s[c + 1]), 0.f);
            v.z = fmaxf(fmaf(a.z + bb_s[c + 2], sc_s[c + 2], sh_s[c + 2]), 0.f);
            v.w = fmaxf(fmaf(a.w + bb_s[c + 3], sc_s[c + 3], sh_s[c + 3]), 0.f);
        }
        *(float4*)&Zs[r * 36 + q * 4] = v;
    }
    __syncthreads();

    int cg = tid & 7, rg = tid >> 3;
    float acc[4][4] = {};
    #pragma unroll
    for (int kq = 0; kq < 8; kq++) {
        float4 b0 = *(const float4*)&Ws[(kq * 4 + 0) * HID + cg * 4];
        float4 b1v = *(const float4*)&Ws[(kq * 4 + 1) * HID + cg * 4];
        float4 b2v = *(const float4*)&Ws[(kq * 4 + 2) * HID + cg * 4];
        float4 b3v = *(const float4*)&Ws[(kq * 4 + 3) * HID + cg * 4];
        #pragma unroll
        for (int ri = 0; ri < 4; ri++) {
            float4 a4 = *(const float4*)&Zs[(rg * 4 + ri) * 36 + kq * 4];
            acc[ri][0] += a4.x * b0.x; acc[ri][1] += a4.x * b0.y;
            acc[ri][2] += a4.x * b0.z; acc[ri][3] += a4.x * b0.w;
            acc[ri][0] += a4.y * b1v.x; acc[ri][1] += a4.y * b1v.y;
            acc[ri][2] += a4.y * b1v.z; acc[ri][3] += a4.y * b1v.w;
            acc[ri][0] += a4.z * b2v.x; acc[ri][1] += a4.z * b2v.y;
            acc[ri][2] += a4.z * b2v.z; acc[ri][3] += a4.z * b2v.w;
            acc[ri][0] += a4.w * b3v.x; acc[ri][1] += a4.w * b3v.y;
            acc[ri][2] += a4.w * b3v.z; acc[ri][3] += a4.w * b3v.w;
        }
    }
    #pragma unroll
    for (int ri = 0; ri < 4; ri++) {
        int r = rowbase + rg * 4 + ri;
        if (r < N_NODES) {
            float dinv = rsqrtf(1.0f + (float)g_cnt[r]);
            float4 v = make_float4(acc[ri][0] * dinv, acc[ri][1] * dinv,
                                   acc[ri][2] * dinv, acc[ri][3] * dinv);
            *(float4*)&g_hs2[(size_t)r * HID + cg * 4] = v;
        }
    }
}

// ---------------------------------------------------------------
extern "C" void kernel_launch(void* const* d_in, const int* in_sizes, int n_in,
                              void* d_out, int out_size) {
    const float* x     = (const float*)d_in[0];
    const int*   ei    = (const int*)d_in[1];   // int32
    const float* W1    = (const float*)d_in[2];
    const float* b1    = (const float*)d_in[3];
    const float* gamma = (const float*)d_in[4];
    const float* beta  = (const float*)d_in[5];
    const float* W2    = (const float*)d_in[6];
    const float* b2    = (const float*)d_in[7];
    float* out = (float*)d_out;

    const int* esrc = ei;
    const int* edst = ei + N_EDGES;

    k_init   <<<(N_NODES + 255) / 256, 256>>>();
    k_fill   <<<(N_EDGES / 4 + 255) / 256, 256>>>(esrc, edst);
    k_pad    <<<(N_NODES * 32 + 255) / 256, 256>>>();
    k_gemm1  <<<(N_NODES + 127) / 128, 256>>>(x, W1);
    k_pull1  <<<(N_NODES * 32) / 256, 256>>>();
    k_bnstats<<<592, 256>>>(b1);
    k_bnfin  <<<1, 32>>>(gamma, beta);
    k_gemm2  <<<(N_NODES + 127) / 128, 256>>>(b1, W2);
    k_pull2  <<<(N_NODES * 32) / 256, 256>>>(b2, out);
}

// round 9
// speedup vs baseline: 1.3738x; 1.1353x over previous
#include <cuda_runtime.h>

#define N_NODES 100000
#define N_EDGES 1600000
#define IN_DIM 128
#define HID 32
#define BN_EPS 1e-5f
#define CAP 96   // max in-degree capacity (Poisson(16); P(deg>=96) ~ 1e-46); %4==0

// ---- scratch (static device globals; no allocation allowed) ----
__device__ __align__(128) int   g_cnt[N_NODES];
__device__ __align__(128) int   g_slots[N_NODES * CAP];
__device__ __align__(128) float g_hs1[N_NODES * HID];
__device__ __align__(128) float g_z1[N_NODES * HID];
__device__ __align__(128) float g_hs2[N_NODES * HID];
__device__ float g_sums[64];   // [0:32) sum, [32:64) sumsq
__device__ float g_bn[64];     // kept for layout compat (unused now)

// ---------------------------------------------------------------
__global__ void k_init() {
    int i = blockIdx.x * blockDim.x + threadIdx.x;
    if (i < N_NODES) g_cnt[i] = 0;
    if (i < 64) g_sums[i] = 0.0f;
}

__global__ void k_fill(const int* __restrict__ src, const int* __restrict__ dst) {
    int t = blockIdx.x * blockDim.x + threadIdx.x;
    int e0 = t * 4;
    if (e0 >= N_EDGES) return;
    int4 d4 = *(const int4*)&dst[e0];
    int4 s4 = *(const int4*)&src[e0];
    int pos;
    pos = atomicAdd(&g_cnt[d4.x], 1); if (pos < CAP) g_slots[d4.x * CAP + pos] = s4.x;
    pos = atomicAdd(&g_cnt[d4.y], 1); if (pos < CAP) g_slots[d4.y * CAP + pos] = s4.y;
    pos = atomicAdd(&g_cnt[d4.z], 1); if (pos < CAP) g_slots[d4.z * CAP + pos] = s4.z;
    pos = atomicAdd(&g_cnt[d4.w], 1); if (pos < CAP) g_slots[d4.w * CAP + pos] = s4.w;
}

// ---------------------------------------------------------------
// 3) GEMM1: hs1[r] = (x[r] @ W1) * dinv[r]   (round-5 body, occ-4 bound)
__global__ void __launch_bounds__(256, 4) k_gemm1(const float* __restrict__ x,
                                                  const float* __restrict__ W1) {
    __shared__ float Ws[IN_DIM * HID];   // 16KB
    __shared__ float Xs[128 * 36];       // 18KB padded
    int tid = threadIdx.x;
    int rowbase = blockIdx.x * 128;

    for (int i = tid; i < IN_DIM * HID / 4; i += 256)
        ((float4*)Ws)[i] = ((const float4*)W1)[i];

    int cg = tid & 7;    // cols cg*4..cg*4+3
    int rg = tid >> 3;   // rows rg*4..rg*4+3
    float acc[4][4] = {};

    for (int kb = 0; kb < IN_DIM; kb += 32) {
        __syncthreads();
        #pragma unroll
        for (int j = 0; j < 4; j++) {
            int idx = tid + j * 256;
            int r = idx >> 3, q = idx & 7;
            int gr = rowbase + r;
            float4 v = make_float4(0.f, 0.f, 0.f, 0.f);
            if (gr < N_NODES) v = *(const float4*)&x[(size_t)gr * IN_DIM + kb + q * 4];
            *(float4*)&Xs[r * 36 + q * 4] = v;
        }
        __syncthreads();
        #pragma unroll
        for (int k = 0; k < 32; k++) {
            float4 b4 = *(const float4*)&Ws[(kb + k) * HID + cg * 4];
            #pragma unroll
            for (int ri = 0; ri < 4; ri++) {
                float a = Xs[(rg * 4 + ri) * 36 + k];
                acc[ri][0] += a * b4.x; acc[ri][1] += a * b4.y;
                acc[ri][2] += a * b4.z; acc[ri][3] += a * b4.w;
            }
        }
    }
    #pragma unroll
    for (int ri = 0; ri < 4; ri++) {
        int r = rowbase + rg * 4 + ri;
        if (r < N_NODES) {
            float dinv = rsqrtf(1.0f + (float)g_cnt[r]);
            float4 v = make_float4(acc[ri][0] * dinv, acc[ri][1] * dinv,
                                   acc[ri][2] * dinv, acc[ri][3] * dinv);
            *(float4*)&g_hs1[(size_t)r * HID + cg * 4] = v;
        }
    }
}

// ---------------------------------------------------------------
// pull body (round-5, best measured): one warp per node, 4 subwarps x 8 lanes,
// guarded 4-edge rounds; one LDG.128 warp-instruction gathers 4 edges.
__device__ __forceinline__ float4 pull_node(const float* __restrict__ hs, int n, int lane) {
    int cnt = g_cnt[n];
    int rem = min(cnt, CAP);
    int sw = lane >> 3;          // subwarp 0..3
    int q  = lane & 7;           // float4 slot within row
    const int* base = &g_slots[(size_t)n * CAP];

    float4 acc;
    if (sw == 0) {               // self loop handled by subwarp 0
        acc = *(const float4*)&hs[(size_t)n * HID + q * 4];
    } else {
        acc = make_float4(0.f, 0.f, 0.f, 0.f);
    }

    for (int j0 = 0; j0 < rem; j0 += 4) {
        int jj = j0 + sw;
        if (jj < rem) {
            int s = base[jj];
            float4 v = *(const float4*)&hs[(size_t)s * HID + q * 4];
            acc.x += v.x; acc.y += v.y; acc.z += v.z; acc.w += v.w;
        }
    }

    #pragma unroll
    for (int off = 8; off <= 16; off <<= 1) {
        acc.x += __shfl_xor_sync(0xffffffffu, acc.x, off);
        acc.y += __shfl_xor_sync(0xffffffffu, acc.y, off);
        acc.z += __shfl_xor_sync(0xffffffffu, acc.z, off);
        acc.w += __shfl_xor_sync(0xffffffffu, acc.w, off);
    }
    float dinv = rsqrtf(1.0f + (float)cnt);
    acc.x *= dinv; acc.y *= dinv; acc.z *= dinv; acc.w *= dinv;
    return acc;
}

__global__ void k_pull1() {
    int w = (blockIdx.x * blockDim.x + threadIdx.x) >> 5;
    int lane = threadIdx.x & 31;
    if (w >= N_NODES) return;
    float4 r = pull_node(g_hs1, w, lane);
    if (lane < 8)
        *(float4*)&g_z1[(size_t)w * HID + lane * 4] = r;
}

__global__ void k_pull2(const float* __restrict__ b2, float* __restrict__ out) {
    int w = (blockIdx.x * blockDim.x + threadIdx.x) >> 5;
    int lane = threadIdx.x & 31;
    if (w >= N_NODES) return;
    float4 r = pull_node(g_hs2, w, lane);
    if (lane < 8) {
        float4 bb = *(const float4*)&b2[lane * 4];
        r.x += bb.x; r.y += bb.y; r.z += bb.z; r.w += bb.w;
        *(float4*)&out[(size_t)w * HID + lane * 4] = r;
    }
}

// ---------------------------------------------------------------
// 5) BN stats over v = z1 + b1
__global__ void k_bnstats(const float* __restrict__ b1) {
    __shared__ float ss[256], sq[256];
    int tid = threadIdx.x;
    int c = tid & 31, rs = tid >> 5;
    int chunk = (N_NODES + gridDim.x - 1) / gridDim.x;
    int r0 = blockIdx.x * chunk;
    int r1 = min(r0 + chunk, N_NODES);
    float bc = b1[c];
    float s = 0.f, s2 = 0.f;
    for (int r = r0 + rs; r < r1; r += 8) {
        float v = g_z1[(size_t)r * HID + c] + bc;
        s += v; s2 += v * v;
    }
    ss[tid] = s; sq[tid] = s2;
    __syncthreads();
    if (tid < 128) { ss[tid] += ss[tid + 128]; sq[tid] += sq[tid + 128]; }
    __syncthreads();
    if (tid < 64) { ss[tid] += ss[tid + 64]; sq[tid] += sq[tid + 64]; }
    __syncthreads();
    if (tid < 32) {
        atomicAdd(&g_sums[c], ss[tid] + ss[tid + 32]);
        atomicAdd(&g_sums[32 + c], sq[tid] + sq[tid + 32]);
    }
}

// ---------------------------------------------------------------
// 7) GEMM2 (bnfin fused): z = relu(BN(z1 + b1)); hs2 = (z@W2)*dinv
__global__ void k_gemm2(const float* __restrict__ b1, const float* __restrict__ gamma,
                        const float* __restrict__ beta, const float* __restrict__ W2) {
    __shared__ float Ws[HID * HID];
    __shared__ float Zs[128 * 36];
    __shared__ float sc_s[32], sh_s[32], bb_s[32];
    int tid = threadIdx.x;
    int rowbase = blockIdx.x * 128;

    if (tid < 32) {
        // BN finalize, computed redundantly per block (cheap)
        float mean = g_sums[tid] * (1.0f / N_NODES);
        float var = g_sums[32 + tid] * (1.0f / N_NODES) - mean * mean;
        var = fmaxf(var, 0.f);
        float sc = gamma[tid] * rsqrtf(var + BN_EPS);
        sc_s[tid] = sc;
        sh_s[tid] = beta[tid] - mean * sc;
        bb_s[tid] = b1[tid];
    }
    for (int i = tid; i < HID * HID / 4; i += 256)
        ((float4*)Ws)[i] = ((const float4*)W2)[i];
    __syncthreads();

    #pragma unroll
    for (int j = 0; j < 4; j++) {
        int idx = tid + j * 256;
        int r = idx >> 3, q = idx & 7;
        int gr = rowbase + r;
        float4 v = make_float4(0.f, 0.f, 0.f, 0.f);
        if (gr < N_NODES) {
            float4 a = *(const float4*)&g_z1[(size_t)gr * HID + q * 4];
            int c = q * 4;
            v.x = fmaxf(fmaf(a.x + bb_s[c + 0], sc_s[c + 0], sh_s[c + 0]), 0.f);
            v.y = fmaxf(fmaf(a.y + bb_s[c + 1], sc_s[c + 1], sh_s[c + 1]), 0.f);
            v.z = fmaxf(fmaf(a.z + bb_s[c + 2], sc_s[c + 2], sh_s[c + 2]), 0.f);
            v.w = fmaxf(fmaf(a.w + bb_s[c + 3], sc_s[c + 3], sh_s[c + 3]), 0.f);
        }
        *(float4*)&Zs[r * 36 + q * 4] = v;
    }
    __syncthreads();

    int cg = tid & 7, rg = tid >> 3;
    float acc[4][4] = {};
    #pragma unroll
    for (int k = 0; k < 32; k++) {
        float4 b4 = *(const float4*)&Ws[k * HID + cg * 4];
        #pragma unroll
        for (int ri = 0; ri < 4; ri++) {
            float a = Zs[(rg * 4 + ri) * 36 + k];
            acc[ri][0] += a * b4.x; acc[ri][1] += a * b4.y;
            acc[ri][2] += a * b4.z; acc[ri][3] += a * b4.w;
        }
    }
    #pragma unroll
    for (int ri = 0; ri < 4; ri++) {
        int r = rowbase + rg * 4 + ri;
        if (r < N_NODES) {
            float dinv = rsqrtf(1.0f + (float)g_cnt[r]);
            float4 v = make_float4(acc[ri][0] * dinv, acc[ri][1] * dinv,
                                   acc[ri][2] * dinv, acc[ri][3] * dinv);
            *(float4*)&g_hs2[(size_t)r * HID + cg * 4] = v;
        }
    }
}

// ---------------------------------------------------------------
extern "C" void kernel_launch(void* const* d_in, const int* in_sizes, int n_in,
                              void* d_out, int out_size) {
    const float* x     = (const float*)d_in[0];
    const int*   ei    = (const int*)d_in[1];   // int32
    const float* W1    = (const float*)d_in[2];
    const float* b1    = (const float*)d_in[3];
    const float* gamma = (const float*)d_in[4];
    const float* beta  = (const float*)d_in[5];
    const float* W2    = (const float*)d_in[6];
    const float* b2    = (const float*)d_in[7];
    float* out = (float*)d_out;

    const int* esrc = ei;
    const int* edst = ei + N_EDGES;

    k_init   <<<(N_NODES + 255) / 256, 256>>>();
    k_fill   <<<(N_EDGES / 4 + 255) / 256, 256>>>(esrc, edst);
    k_gemm1  <<<(N_NODES + 127) / 128, 256>>>(x, W1);
    k_pull1  <<<(N_NODES * 32) / 256, 256>>>();
    k_bnstats<<<592, 256>>>(b1);
    k_gemm2  <<<(N_NODES + 127) / 128, 256>>>(b1, gamma, beta, W2);
    k_pull2  <<<(N_NODES * 32) / 256, 256>>>(b2, out);
}

// round 10
// speedup vs baseline: 1.3944x; 1.0150x over previous
#include <cuda_runtime.h>

#define N_NODES 100000
#define N_EDGES 1600000
#define IN_DIM 128
#define HID 32
#define BN_EPS 1e-5f
#define CAP 96   // max in-degree capacity (Poisson(16); P(deg>=96) ~ 1e-46); %4==0

// ---- scratch (static device globals; no allocation allowed) ----
__device__ __align__(128) int   g_cnt[N_NODES];
__device__ __align__(128) int   g_slots[N_NODES * CAP];
__device__ __align__(128) float g_hs1[N_NODES * HID];
__device__ __align__(128) float g_z1[N_NODES * HID];
__device__ __align__(128) float g_hs2[N_NODES * HID];
__device__ float g_sums[64];   // [0:32) sum, [32:64) sumsq

// ---------------------------------------------------------------
__global__ void k_init() {
    int i = blockIdx.x * blockDim.x + threadIdx.x;
    if (i < N_NODES) g_cnt[i] = 0;
    if (i < 64) g_sums[i] = 0.0f;
}

__global__ void k_fill(const int* __restrict__ src, const int* __restrict__ dst) {
    int t = blockIdx.x * blockDim.x + threadIdx.x;
    int e0 = t * 4;
    if (e0 >= N_EDGES) return;
    int4 d4 = *(const int4*)&dst[e0];
    int4 s4 = *(const int4*)&src[e0];
    int pos;
    pos = atomicAdd(&g_cnt[d4.x], 1); if (pos < CAP) g_slots[d4.x * CAP + pos] = s4.x;
    pos = atomicAdd(&g_cnt[d4.y], 1); if (pos < CAP) g_slots[d4.y * CAP + pos] = s4.y;
    pos = atomicAdd(&g_cnt[d4.z], 1); if (pos < CAP) g_slots[d4.z * CAP + pos] = s4.z;
    pos = atomicAdd(&g_cnt[d4.w], 1); if (pos < CAP) g_slots[d4.w * CAP + pos] = s4.w;
}

// ---------------------------------------------------------------
// 3) GEMM1: hs1[r] = (x[r] @ W1) * dinv[r]
__global__ void __launch_bounds__(256, 4) k_gemm1(const float* __restrict__ x,
                                                  const float* __restrict__ W1) {
    __shared__ float Ws[IN_DIM * HID];   // 16KB
    __shared__ float Xs[128 * 36];       // 18KB padded
    int tid = threadIdx.x;
    int rowbase = blockIdx.x * 128;

    for (int i = tid; i < IN_DIM * HID / 4; i += 256)
        ((float4*)Ws)[i] = ((const float4*)W1)[i];

    int cg = tid & 7;
    int rg = tid >> 3;
    float acc[4][4] = {};

    for (int kb = 0; kb < IN_DIM; kb += 32) {
        __syncthreads();
        #pragma unroll
        for (int j = 0; j < 4; j++) {
            int idx = tid + j * 256;
            int r = idx >> 3, q = idx & 7;
            int gr = rowbase + r;
            float4 v = make_float4(0.f, 0.f, 0.f, 0.f);
            if (gr < N_NODES) v = *(const float4*)&x[(size_t)gr * IN_DIM + kb + q * 4];
            *(float4*)&Xs[r * 36 + q * 4] = v;
        }
        __syncthreads();
        #pragma unroll
        for (int k = 0; k < 32; k++) {
            float4 b4 = *(const float4*)&Ws[(kb + k) * HID + cg * 4];
            #pragma unroll
            for (int ri = 0; ri < 4; ri++) {
                float a = Xs[(rg * 4 + ri) * 36 + k];
                acc[ri][0] += a * b4.x; acc[ri][1] += a * b4.y;
                acc[ri][2] += a * b4.z; acc[ri][3] += a * b4.w;
            }
        }
    }
    #pragma unroll
    for (int ri = 0; ri < 4; ri++) {
        int r = rowbase + rg * 4 + ri;
        if (r < N_NODES) {
            float dinv = rsqrtf(1.0f + (float)g_cnt[r]);
            float4 v = make_float4(acc[ri][0] * dinv, acc[ri][1] * dinv,
                                   acc[ri][2] * dinv, acc[ri][3] * dinv);
            *(float4*)&g_hs1[(size_t)r * HID + cg * 4] = v;
        }
    }
}

// ---------------------------------------------------------------
// pull body: one warp per node, 4 subwarps x 8 lanes.
// Phase 1: ONE warp-wide int4 burst loads the whole slot list (all index-DRAM
//          latency paid once, in parallel) into per-warp smem.
// Phase 2: guarded 4-edge gather rounds; indices come from smem (29 cyc)
//          so the L2 gathers pipeline deeply.
__device__ __forceinline__ float4 pull_node(const float* __restrict__ hs, int n,
                                            int lane, int* __restrict__ sidx) {
    int cnt = g_cnt[n];
    int rem = min(cnt, CAP);
    int sw = lane >> 3;          // subwarp 0..3
    int q  = lane & 7;           // float4 slot within row
    const int* base = &g_slots[(size_t)n * CAP];

    // burst: lane l loads idx[4l..4l+3] if in range (lanes 0..23 cover CAP=96)
    if (lane * 4 < rem) {
        int4 v = *(const int4*)&base[lane * 4];
        *(int4*)&sidx[lane * 4] = v;
    }
    __syncwarp();

    float4 acc;
    if (sw == 0) {               // self loop handled by subwarp 0
        acc = *(const float4*)&hs[(size_t)n * HID + q * 4];
    } else {
        acc = make_float4(0.f, 0.f, 0.f, 0.f);
    }

    for (int j0 = 0; j0 < rem; j0 += 4) {
        int jj = j0 + sw;
        if (jj < rem) {
            int s = sidx[jj];
            float4 v = *(const float4*)&hs[(size_t)s * HID + q * 4];
            acc.x += v.x; acc.y += v.y; acc.z += v.z; acc.w += v.w;
        }
    }
    __syncwarp();

    #pragma unroll
    for (int off = 8; off <= 16; off <<= 1) {
        acc.x += __shfl_xor_sync(0xffffffffu, acc.x, off);
        acc.y += __shfl_xor_sync(0xffffffffu, acc.y, off);
        acc.z += __shfl_xor_sync(0xffffffffu, acc.z, off);
        acc.w += __shfl_xor_sync(0xffffffffu, acc.w, off);
    }
    float dinv = rsqrtf(1.0f + (float)cnt);
    acc.x *= dinv; acc.y *= dinv; acc.z *= dinv; acc.w *= dinv;
    return acc;
}

__global__ void k_pull1() {
    __shared__ __align__(16) int sidx[8][CAP];   // 3KB: per-warp index stash
    int w = (blockIdx.x * blockDim.x + threadIdx.x) >> 5;
    int lane = threadIdx.x & 31;
    int wslot = threadIdx.x >> 5;
    if (w >= N_NODES) return;
    float4 r = pull_node(g_hs1, w, lane, sidx[wslot]);
    if (lane < 8)
        *(float4*)&g_z1[(size_t)w * HID + lane * 4] = r;
}

__global__ void k_pull2(const float* __restrict__ b2, float* __restrict__ out) {
    __shared__ __align__(16) int sidx[8][CAP];
    int w = (blockIdx.x * blockDim.x + threadIdx.x) >> 5;
    int lane = threadIdx.x & 31;
    int wslot = threadIdx.x >> 5;
    if (w >= N_NODES) return;
    float4 r = pull_node(g_hs2, w, lane, sidx[wslot]);
    if (lane < 8) {
        float4 bb = *(const float4*)&b2[lane * 4];
        r.x += bb.x; r.y += bb.y; r.z += bb.z; r.w += bb.w;
        *(float4*)&out[(size_t)w * HID + lane * 4] = r;
    }
}

// ---------------------------------------------------------------
// 5) BN stats over v = z1 + b1
__global__ void k_bnstats(const float* __restrict__ b1) {
    __shared__ float ss[256], sq[256];
    int tid = threadIdx.x;
    int c = tid & 31, rs = tid >> 5;
    int chunk = (N_NODES + gridDim.x - 1) / gridDim.x;
    int r0 = blockIdx.x * chunk;
    int r1 = min(r0 + chunk, N_NODES);
    float bc = b1[c];
    float s = 0.f, s2 = 0.f;
    for (int r = r0 + rs; r < r1; r += 8) {
        float v = g_z1[(size_t)r * HID + c] + bc;
        s += v; s2 += v * v;
    }
    ss[tid] = s; sq[tid] = s2;
    __syncthreads();
    if (tid < 128) { ss[tid] += ss[tid + 128]; sq[tid] += sq[tid + 128]; }
    __syncthreads();
    if (tid < 64) { ss[tid] += ss[tid + 64]; sq[tid] += sq[tid + 64]; }
    __syncthreads();
    if (tid < 32) {
        atomicAdd(&g_sums[c], ss[tid] + ss[tid + 32]);
        atomicAdd(&g_sums[32 + c], sq[tid] + sq[tid + 32]);
    }
}

// ---------------------------------------------------------------
// 7) GEMM2 (bnfin fused): z = relu(BN(z1 + b1)); hs2 = (z@W2)*dinv
__global__ void k_gemm2(const float* __restrict__ b1, const float* __restrict__ gamma,
                        const float* __restrict__ beta, const float* __restrict__ W2) {
    __shared__ float Ws[HID * HID];
    __shared__ float Zs[128 * 36];
    __shared__ float sc_s[32], sh_s[32], bb_s[32];
    int tid = threadIdx.x;
    int rowbase = blockIdx.x * 128;

    if (tid < 32) {
        float mean = g_sums[tid] * (1.0f / N_NODES);
        float var = g_sums[32 + tid] * (1.0f / N_NODES) - mean * mean;
        var = fmaxf(var, 0.f);
        float sc = gamma[tid] * rsqrtf(var + BN_EPS);
        sc_s[tid] = sc;
        sh_s[tid] = beta[tid] - mean * sc;
        bb_s[tid] = b1[tid];
    }
    for (int i = tid; i < HID * HID / 4; i += 256)
        ((float4*)Ws)[i] = ((const float4*)W2)[i];
    __syncthreads();

    #pragma unroll
    for (int j = 0; j < 4; j++) {
        int idx = tid + j * 256;
        int r = idx >> 3, q = idx & 7;
        int gr = rowbase + r;
        float4 v = make_float4(0.f, 0.f, 0.f, 0.f);
        if (gr < N_NODES) {
            float4 a = *(const float4*)&g_z1[(size_t)gr * HID + q * 4];
            int c = q * 4;
            v.x = fmaxf(fmaf(a.x + bb_s[c + 0], sc_s[c + 0], sh_s[c + 0]), 0.f);
            v.y = fmaxf(fmaf(a.y + bb_s[c + 1], sc_s[c + 1], sh_s[c + 1]), 0.f);
            v.z = fmaxf(fmaf(a.z + bb_s[c + 2], sc_s[c + 2], sh_s[c + 2]), 0.f);
            v.w = fmaxf(fmaf(a.w + bb_s[c + 3], sc_s[c + 3], sh_s[c + 3]), 0.f);
        }
        *(float4*)&Zs[r * 36 + q * 4] = v;
    }
    __syncthreads();

    int cg = tid & 7, rg = tid >> 3;
    float acc[4][4] = {};
    #pragma unroll
    for (int k = 0; k < 32; k++) {
        float4 b4 = *(const float4*)&Ws[k * HID + cg * 4];
        #pragma unroll
        for (int ri = 0; ri < 4; ri++) {
            float a = Zs[(rg * 4 + ri) * 36 + k];
            acc[ri][0] += a * b4.x; acc[ri][1] += a * b4.y;
            acc[ri][2] += a * b4.z; acc[ri][3] += a * b4.w;
        }
    }
    #pragma unroll
    for (int ri = 0; ri < 4; ri++) {
        int r = rowbase + rg * 4 + ri;
        if (r < N_NODES) {
            float dinv = rsqrtf(1.0f + (float)g_cnt[r]);
            float4 v = make_float4(acc[ri][0] * dinv, acc[ri][1] * dinv,
                                   acc[ri][2] * dinv, acc[ri][3] * dinv);
            *(float4*)&g_hs2[(size_t)r * HID + cg * 4] = v;
        }
    }
}

// ---------------------------------------------------------------
extern "C" void kernel_launch(void* const* d_in, const int* in_sizes, int n_in,
                              void* d_out, int out_size) {
    const float* x     = (const float*)d_in[0];
    const int*   ei    = (const int*)d_in[1];   // int32
    const float* W1    = (const float*)d_in[2];
    const float* b1    = (const float*)d_in[3];
    const float* gamma = (const float*)d_in[4];
    const float* beta  = (const float*)d_in[5];
    const float* W2    = (const float*)d_in[6];
    const float* b2    = (const float*)d_in[7];
    float* out = (float*)d_out;

    const int* esrc = ei;
    const int* edst = ei + N_EDGES;

    k_init   <<<(N_NODES + 255) / 256, 256>>>();
    k_fill   <<<(N_EDGES / 4 + 255) / 256, 256>>>(esrc, edst);
    k_gemm1  <<<(N_NODES + 127) / 128, 256>>>(x, W1);
    k_pull1  <<<(N_NODES * 32) / 256, 256>>>();
    k_bnstats<<<592, 256>>>(b1);
    k_gemm2  <<<(N_NODES + 127) / 128, 256>>>(b1, gamma, beta, W2);
    k_pull2  <<<(N_NODES * 32) / 256, 256>>>(b2, out);
}

// round 11
// speedup vs baseline: 1.4699x; 1.0542x over previous
#include <cuda_runtime.h>

#define N_NODES 100000
#define N_EDGES 1600000
#define IN_DIM 128
#define HID 32
#define BN_EPS 1e-5f
#define CAP 96   // max in-degree capacity (Poisson(16); P(deg>=96) ~ 1e-46); %4==0

// ---- scratch (static device globals; no allocation allowed) ----
__device__ __align__(128) int   g_cnt[N_NODES];
__device__ __align__(128) int   g_slots[N_NODES * CAP];
__device__ __align__(128) float g_hs1[N_NODES * HID];
__device__ __align__(128) float g_z1[N_NODES * HID];
__device__ __align__(128) float g_hs2[N_NODES * HID];
__device__ float g_sums[64];   // [0:32) sum, [32:64) sumsq

// ---------------------------------------------------------------
__global__ void k_init() {
    int i = blockIdx.x * blockDim.x + threadIdx.x;
    if (i < N_NODES) g_cnt[i] = 0;
    if (i < 64) g_sums[i] = 0.0f;
}

__global__ void k_fill(const int* __restrict__ src, const int* __restrict__ dst) {
    int t = blockIdx.x * blockDim.x + threadIdx.x;
    int e0 = t * 4;
    if (e0 >= N_EDGES) return;
    int4 d4 = *(const int4*)&dst[e0];
    int4 s4 = *(const int4*)&src[e0];
    int pos;
    pos = atomicAdd(&g_cnt[d4.x], 1); if (pos < CAP) g_slots[d4.x * CAP + pos] = s4.x;
    pos = atomicAdd(&g_cnt[d4.y], 1); if (pos < CAP) g_slots[d4.y * CAP + pos] = s4.y;
    pos = atomicAdd(&g_cnt[d4.z], 1); if (pos < CAP) g_slots[d4.z * CAP + pos] = s4.z;
    pos = atomicAdd(&g_cnt[d4.w], 1); if (pos < CAP) g_slots[d4.w * CAP + pos] = s4.w;
}

// ---------------------------------------------------------------
// 3) GEMM1: hs1[r] = (x[r] @ W1) * dinv[r]
__global__ void __launch_bounds__(256, 4) k_gemm1(const float* __restrict__ x,
                                                  const float* __restrict__ W1) {
    __shared__ float Ws[IN_DIM * HID];   // 16KB
    __shared__ float Xs[128 * 36];       // 18KB padded
    int tid = threadIdx.x;
    int rowbase = blockIdx.x * 128;

    for (int i = tid; i < IN_DIM * HID / 4; i += 256)
        ((float4*)Ws)[i] = ((const float4*)W1)[i];

    int cg = tid & 7;
    int rg = tid >> 3;
    float acc[4][4] = {};

    for (int kb = 0; kb < IN_DIM; kb += 32) {
        __syncthreads();
        #pragma unroll
        for (int j = 0; j < 4; j++) {
            int idx = tid + j * 256;
            int r = idx >> 3, q = idx & 7;
            int gr = rowbase + r;
            float4 v = make_float4(0.f, 0.f, 0.f, 0.f);
            if (gr < N_NODES) v = *(const float4*)&x[(size_t)gr * IN_DIM + kb + q * 4];
            *(float4*)&Xs[r * 36 + q * 4] = v;
        }
        __syncthreads();
        #pragma unroll
        for (int k = 0; k < 32; k++) {
            float4 b4 = *(const float4*)&Ws[(kb + k) * HID + cg * 4];
            #pragma unroll
            for (int ri = 0; ri < 4; ri++) {
                float a = Xs[(rg * 4 + ri) * 36 + k];
                acc[ri][0] += a * b4.x; acc[ri][1] += a * b4.y;
                acc[ri][2] += a * b4.z; acc[ri][3] += a * b4.w;
            }
        }
    }
    #pragma unroll
    for (int ri = 0; ri < 4; ri++) {
        int r = rowbase + rg * 4 + ri;
        if (r < N_NODES) {
            float dinv = rsqrtf(1.0f + (float)g_cnt[r]);
            float4 v = make_float4(acc[ri][0] * dinv, acc[ri][1] * dinv,
                                   acc[ri][2] * dinv, acc[ri][3] * dinv);
            *(float4*)&g_hs1[(size_t)r * HID + cg * 4] = v;
        }
    }
}

// ---------------------------------------------------------------
// pull body: one warp handles 4 consecutive nodes; each 8-lane group owns one
// node end-to-end. No cross-group folding: group lanes hold the full 128B row.
// Per inner iteration, one LDG.128 gathers 4 rows (one per group).
__device__ __forceinline__ float4 pull4(const float* __restrict__ hs, int wbase,
                                        int lane, int* __restrict__ sidx /*4*CAP*/) {
    int sw = lane >> 3;          // group 0..3 -> node
    int gl = lane & 7;           // lane within group (float4 slot)
    int n = wbase + sw;
    int cnt = g_cnt[n];
    int rem = min(cnt, CAP);
    const int* base = &g_slots[(size_t)n * CAP];
    int* sg = sidx + sw * CAP;

    // burst this group's index list into smem (rounds of 32 idx per group)
    for (int jb = 0; jb < rem; jb += 32) {
        int p = jb + gl * 4;
        if (p < rem) *(int4*)&sg[p] = *(const int4*)&base[p];
    }
    __syncwarp();

    float4 acc = *(const float4*)&hs[(size_t)n * HID + gl * 4];   // self loop

    for (int j = 0; j < rem; j++) {
        int s = sg[j];
        float4 v = *(const float4*)&hs[(size_t)s * HID + gl * 4];
        acc.x += v.x; acc.y += v.y; acc.z += v.z; acc.w += v.w;
    }

    float dinv = rsqrtf(1.0f + (float)cnt);
    acc.x *= dinv; acc.y *= dinv; acc.z *= dinv; acc.w *= dinv;
    return acc;   // every lane holds its float4 chunk of node n's output row
}

__global__ void k_pull1() {
    __shared__ __align__(16) int sidx[8][4 * CAP];   // 12KB: per-warp, per-group idx
    int warp = (blockIdx.x * blockDim.x + threadIdx.x) >> 5;
    int lane = threadIdx.x & 31;
    int wslot = threadIdx.x >> 5;
    int wbase = warp * 4;
    if (wbase >= N_NODES) return;
    float4 r = pull4(g_hs1, wbase, lane, sidx[wslot]);
    int n = wbase + (lane >> 3);
    *(float4*)&g_z1[(size_t)n * HID + (lane & 7) * 4] = r;
}

__global__ void k_pull2(const float* __restrict__ b2, float* __restrict__ out) {
    __shared__ __align__(16) int sidx[8][4 * CAP];
    int warp = (blockIdx.x * blockDim.x + threadIdx.x) >> 5;
    int lane = threadIdx.x & 31;
    int wslot = threadIdx.x >> 5;
    int wbase = warp * 4;
    if (wbase >= N_NODES) return;
    float4 r = pull4(g_hs2, wbase, lane, sidx[wslot]);
    float4 bb = *(const float4*)&b2[(lane & 7) * 4];
    r.x += bb.x; r.y += bb.y; r.z += bb.z; r.w += bb.w;
    int n = wbase + (lane >> 3);
    *(float4*)&out[(size_t)n * HID + (lane & 7) * 4] = r;
}

// ---------------------------------------------------------------
// 5) BN stats over v = z1 + b1
__global__ void k_bnstats(const float* __restrict__ b1) {
    __shared__ float ss[256], sq[256];
    int tid = threadIdx.x;
    int c = tid & 31, rs = tid >> 5;
    int chunk = (N_NODES + gridDim.x - 1) / gridDim.x;
    int r0 = blockIdx.x * chunk;
    int r1 = min(r0 + chunk, N_NODES);
    float bc = b1[c];
    float s = 0.f, s2 = 0.f;
    for (int r = r0 + rs; r < r1; r += 8) {
        float v = g_z1[(size_t)r * HID + c] + bc;
        s += v; s2 += v * v;
    }
    ss[tid] = s; sq[tid] = s2;
    __syncthreads();
    if (tid < 128) { ss[tid] += ss[tid + 128]; sq[tid] += sq[tid + 128]; }
    __syncthreads();
    if (tid < 64) { ss[tid] += ss[tid + 64]; sq[tid] += sq[tid + 64]; }
    __syncthreads();
    if (tid < 32) {
        atomicAdd(&g_sums[c], ss[tid] + ss[tid + 32]);
        atomicAdd(&g_sums[32 + c], sq[tid] + sq[tid + 32]);
    }
}

// ---------------------------------------------------------------
// 7) GEMM2 (bnfin fused): z = relu(BN(z1 + b1)); hs2 = (z@W2)*dinv
__global__ void k_gemm2(const float* __restrict__ b1, const float* __restrict__ gamma,
                        const float* __restrict__ beta, const float* __restrict__ W2) {
    __shared__ float Ws[HID * HID];
    __shared__ float Zs[128 * 36];
    __shared__ float sc_s[32], sh_s[32], bb_s[32];
    int tid = threadIdx.x;
    int rowbase = blockIdx.x * 128;

    if (tid < 32) {
        float mean = g_sums[tid] * (1.0f / N_NODES);
        float var = g_sums[32 + tid] * (1.0f / N_NODES) - mean * mean;
        var = fmaxf(var, 0.f);
        float sc = gamma[tid] * rsqrtf(var + BN_EPS);
        sc_s[tid] = sc;
        sh_s[tid] = beta[tid] - mean * sc;
        bb_s[tid] = b1[tid];
    }
    for (int i = tid; i < HID * HID / 4; i += 256)
        ((float4*)Ws)[i] = ((const float4*)W2)[i];
    __syncthreads();

    #pragma unroll
    for (int j = 0; j < 4; j++) {
        int idx = tid + j * 256;
        int r = idx >> 3, q = idx & 7;
        int gr = rowbase + r;
        float4 v = make_float4(0.f, 0.f, 0.f, 0.f);
        if (gr < N_NODES) {
            float4 a = *(const float4*)&g_z1[(size_t)gr * HID + q * 4];
            int c = q * 4;
            v.x = fmaxf(fmaf(a.x + bb_s[c + 0], sc_s[c + 0], sh_s[c + 0]), 0.f);
            v.y = fmaxf(fmaf(a.y + bb_s[c + 1], sc_s[c + 1], sh_s[c + 1]), 0.f);
            v.z = fmaxf(fmaf(a.z + bb_s[c + 2], sc_s[c + 2], sh_s[c + 2]), 0.f);
            v.w = fmaxf(fmaf(a.w + bb_s[c + 3], sc_s[c + 3], sh_s[c + 3]), 0.f);
        }
        *(float4*)&Zs[r * 36 + q * 4] = v;
    }
    __syncthreads();

    int cg = tid & 7, rg = tid >> 3;
    float acc[4][4] = {};
    #pragma unroll
    for (int k = 0; k < 32; k++) {
        float4 b4 = *(const float4*)&Ws[k * HID + cg * 4];
        #pragma unroll
        for (int ri = 0; ri < 4; ri++) {
            float a = Zs[(rg * 4 + ri) * 36 + k];
            acc[ri][0] += a * b4.x; acc[ri][1] += a * b4.y;
            acc[ri][2] += a * b4.z; acc[ri][3] += a * b4.w;
        }
    }
    #pragma unroll
    for (int ri = 0; ri < 4; ri++) {
        int r = rowbase + rg * 4 + ri;
        if (r < N_NODES) {
            float dinv = rsqrtf(1.0f + (float)g_cnt[r]);
            float4 v = make_float4(acc[ri][0] * dinv, acc[ri][1] * dinv,
                                   acc[ri][2] * dinv, acc[ri][3] * dinv);
            *(float4*)&g_hs2[(size_t)r * HID + cg * 4] = v;
        }
    }
}

// ---------------------------------------------------------------
extern "C" void kernel_launch(void* const* d_in, const int* in_sizes, int n_in,
                              void* d_out, int out_size) {
    const float* x     = (const float*)d_in[0];
    const int*   ei    = (const int*)d_in[1];   // int32
    const float* W1    = (const float*)d_in[2];
    const float* b1    = (const float*)d_in[3];
    const float* gamma = (const float*)d_in[4];
    const float* beta  = (const float*)d_in[5];
    const float* W2    = (const float*)d_in[6];
    const float* b2    = (const float*)d_in[7];
    float* out = (float*)d_out;

    const int* esrc = ei;
    const int* edst = ei + N_EDGES;

    // 4 nodes per warp -> 25000 warps -> 3125 blocks of 256
    int pull_blocks = (N_NODES / 4 * 32 + 255) / 256;

    k_init   <<<(N_NODES + 255) / 256, 256>>>();
    k_fill   <<<(N_EDGES / 4 + 255) / 256, 256>>>(esrc, edst);
    k_gemm1  <<<(N_NODES + 127) / 128, 256>>>(x, W1);
    k_pull1  <<<pull_blocks, 256>>>();
    k_bnstats<<<592, 256>>>(b1);
    k_gemm2  <<<(N_NODES + 127) / 128, 256>>>(b1, gamma, beta, W2);
    k_pull2  <<<pull_blocks, 256>>>(b2, out);
}